// round 8
// baseline (speedup 1.0000x reference)
#include <cuda_runtime.h>
#include <cstdint>

// ----------------------------------------------------------------------------
// TitleGenerator fused single kernel, round 7.
// 148 CTAs x 608 threads. Thread = (pair pid in [0,304), batch-half bh).
// Each thread computes TWO output rows (A = pid or pid+256; B = A+256 or
// pid+304) over SEVEN batch rows, reusing each x LDS for both rows:
// FMA:LDS ratio 4:1 (was 2:1 -> L1 89% bound in R6 profile).
// Row A weights SMEM-resident (combined r/z sum); row B streamed from L2
// (raw rows >= 256 never need summing), double-buffered.
// Period-2 bitwise fixed-point detection -> replicate remaining outputs.
// ----------------------------------------------------------------------------

#define BB      2048
#define HH      128
#define CC      96
#define TSTEPS  400
#define NT      608
#define NPAIR   304
#define TITLES_ELEMS 78643200        // 2048*400*96

// dynamic smem layout (bytes)
#define OFF_W    0
#define SZ_W     (32 * NPAIR * 16)             // 155648
#define OFF_XH   (OFF_W + SZ_W)                // 155648
#define OFF_XL   (OFF_XH + 14 * 128 * 4)       // 162816
#define OFF_X2   (OFF_XL + 14 * 128 * 4)       // 169984
#define OFF_GSM  (OFF_X2 + 14 * 128 * 4)       // 177152
#define SZ_GSM   (14 * 608 * 4)                // 34048
#define OFF_M4   (OFF_GSM + SZ_GSM)            // 211200
#define OFF_LEN  (OFF_M4 + 256)                // 211456
#define SMEM_TOT (OFF_LEN + 64)                // 211520

typedef unsigned long long ull;

__device__ __forceinline__ void upk2(ull v, float& lo, float& hi) {
    asm("mov.b64 {%0, %1}, %2;" : "=f"(lo), "=f"(hi) : "l"(v));
}
#define FMA2(acc, a, b) asm("fma.rn.f32x2 %0, %1, %2, %3;" : "=l"(acc) : "l"(a), "l"(b), "l"(acc))

__global__ __launch_bounds__(608, 1)
void fused_kernel(float* __restrict__ out,
                  const float* __restrict__ img,
                  const float* __restrict__ lin1_w,
                  const float* __restrict__ lin1_b,
                  const float* __restrict__ w_ih,
                  const float* __restrict__ w_hh,
                  const float* __restrict__ b_ih,
                  const float* __restrict__ b_hh,
                  const float* __restrict__ lin2_w,
                  const float* __restrict__ lin2_b,
                  int hasLens) {
    extern __shared__ __align__(16) char smraw[];
    float4* wsm4 = reinterpret_cast<float4*>(smraw + OFF_W);
    float*  xh   = reinterpret_cast<float*>(smraw + OFF_XH);
    float*  xl   = reinterpret_cast<float*>(smraw + OFF_XL);
    float*  xp2  = reinterpret_cast<float*>(smraw + OFF_X2);
    float*  gsm  = reinterpret_cast<float*>(smraw + OFF_GSM);
    float*  m4   = reinterpret_cast<float*>(smraw + OFF_M4);
    int*    lensm= reinterpret_cast<int*>(smraw + OFF_LEN);

    const int tid = threadIdx.x;
    const int bid = blockIdx.x;
    int base, nv;
    if (bid < 124) { base = bid * 14; nv = 14; }
    else           { base = 1736 + (bid - 124) * 13; nv = 13; }

    const int bh    = (tid >= NPAIR) ? 1 : 0;
    const int pid   = tid - bh * NPAIR;
    const int rbase = bh * 7;
    const int A     = (pid < 256) ? pid : pid + 256;        // smem row
    const int B     = (pid < 256) ? pid + 256 : pid + 304;  // streamed row

    // combined biases
    float biasA, biasB;
    if (A < 256) biasA = b_ih[A] + b_hh[A];
    else         biasA = lin2_b[A - 512];
    if (B < 384)      biasB = b_ih[B];
    else if (B < 512) biasB = b_hh[B - 128];
    else              biasB = lin2_b[B - 512];

    // ---- fill SMEM weights for rows A(pid), layout [g][pid] -----------------
    {
        const float4* wih4 = reinterpret_cast<const float4*>(w_ih);
        const float4* whh4 = reinterpret_cast<const float4*>(w_hh);
        const float4* l2w4 = reinterpret_cast<const float4*>(lin2_w);
        for (int idx = tid; idx < 32 * NPAIR; idx += NT) {
            int g = idx / NPAIR;
            int p = idx - g * NPAIR;
            int row = (p < 256) ? p : p + 256;
            float4 v;
            if (row < 256) {
                float4 a = wih4[row * 32 + g];
                float4 b = whh4[row * 32 + g];
                v = make_float4(a.x + b.x, a.y + b.y, a.z + b.z, a.w + b.w);
            } else {
                v = l2w4[(row - 512) * 32 + g];
            }
            wsm4[idx] = v;
        }
    }

    // zero x buffers, lens
    for (int m = tid; m < 14 * 128; m += NT) { xh[m] = 0.f; xl[m] = 0.f; xp2[m] = 0.f; }
    if (tid < 16) lensm[tid] = 0;

    // ---- Phase A1: lin1 -> ht rows for this CTA (staged in gsm) -------------
    {
        const int j  = tid & 127;
        const int ks = tid >> 7;          // 0..3 for tid<512
        ull acc[14];
#pragma unroll
        for (int r = 0; r < 14; r++) acc[r] = 0ull;

        float4*       xs4 = reinterpret_cast<float4*>(gsm);
        const float4* im4 = reinterpret_cast<const float4*>(img);
        const ulonglong2* xs2 = reinterpret_cast<const ulonglong2*>(gsm);

        for (int kc = 0; kc < 16; kc++) {
            __syncthreads();
            for (int m = tid; m < 14 * 64; m += NT) {
                int r = m >> 6, kk4 = m & 63;
                float4 v = make_float4(0.f, 0.f, 0.f, 0.f);
                if (r < nv) v = im4[(size_t)(base + r) * 1024 + kc * 64 + kk4];
                xs4[r * 64 + kk4] = v;
            }
            __syncthreads();
            if (tid < 512) {
                const ulonglong2* wl = reinterpret_cast<const ulonglong2*>(
                    lin1_w + (size_t)j * 4096 + kc * 256 + ks * 64);
#pragma unroll 4
                for (int q = 0; q < 16; q++) {
                    ulonglong2 wv = wl[q];
#pragma unroll
                    for (int r = 0; r < 14; r++) {
                        ulonglong2 xv = xs2[r * 64 + ks * 16 + q];
                        FMA2(acc[r], wv.x, xv.x);
                        FMA2(acc[r], wv.y, xv.y);
                    }
                }
            }
        }
        __syncthreads();
        if (tid < 512) {
#pragma unroll
            for (int r = 0; r < 14; r++) {
                float lo, hi; upk2(acc[r], lo, hi);
                gsm[r * 512 + ks * 128 + j] = lo + hi;
            }
        }
        __syncthreads();
        for (int m = tid; m < 14 * 128; m += NT) {
            int r = m >> 7, jj = m & 127;
            float v = gsm[r * 512 + jj] + gsm[r * 512 + 128 + jj]
                    + gsm[r * 512 + 256 + jj] + gsm[r * 512 + 384 + jj] + lin1_b[jj];
            xh[r * 128 + jj] = (v >= 0.f) ? v : 0.01f * v;
        }
        __syncthreads();
    }

    // per-thread x source (uniform per thread; only warp 9 mixes)
    const ulonglong2* xs = (pid < 256) ? reinterpret_cast<const ulonglong2*>(xh)
                                       : reinterpret_cast<const ulonglong2*>(xl);
    const ulonglong2* wsm2 = reinterpret_cast<const ulonglong2*>(wsm4);

    // streamed raw weight row B (always >= 256: never needs summing)
    const float* pB;
    if (B < 384)      pB = w_ih  + (size_t)B * 128;
    else if (B < 512) pB = w_hh  + (size_t)(B - 128) * 128;
    else              pB = lin2_w + (size_t)(B - 512) * 128;
    const ulonglong2* wB = reinterpret_cast<const ulonglong2*>(pB);

    auto writeacc = [&](ull* accA, ull* accB) {
#pragma unroll
        for (int r = 0; r < 7; r++) {
            float lo, hi;
            upk2(accA[r], lo, hi);
            gsm[(rbase + r) * 608 + A] = lo + hi + biasA;
            upk2(accB[r], lo, hi);
            gsm[(rbase + r) * 608 + B] = lo + hi + biasB;
        }
    };

    // steady-state matvec: each x granule feeds both weight rows (4:1 FMA:LDS)
    auto matvec = [&]() {
        ull accA[7], accB[7];
#pragma unroll
        for (int r = 0; r < 7; r++) { accA[r] = 0ull; accB[r] = 0ull; }
        ulonglong2 bn[4];
#pragma unroll
        for (int q = 0; q < 4; q++) bn[q] = wB[q];
#pragma unroll 1
        for (int blk = 0; blk < 8; blk++) {
            ulonglong2 b[4], a[4];
#pragma unroll
            for (int q = 0; q < 4; q++) b[q] = bn[q];
            if (blk < 7) {
#pragma unroll
                for (int q = 0; q < 4; q++) bn[q] = wB[blk * 4 + 4 + q];
            }
#pragma unroll
            for (int q = 0; q < 4; q++) a[q] = wsm2[(blk * 4 + q) * NPAIR + pid];
#pragma unroll
            for (int q = 0; q < 4; q++) {
#pragma unroll
                for (int r = 0; r < 7; r++) {
                    ulonglong2 xv = xs[(rbase + r) * 32 + blk * 4 + q];
                    FMA2(accA[r], a[q].x, xv.x);
                    FMA2(accA[r], a[q].y, xv.y);
                    FMA2(accB[r], b[q].x, xv.x);
                    FMA2(accB[r], b[q].y, xv.y);
                }
            }
        }
        writeacc(accA, accB);
    };

    // step-1 matvec: x = ht (in xh), h = 0. Gate rows use raw w_ih; rows >= 384
    // are bias-only; lin2 rows ignored downstream.
    auto matvec1 = [&]() {
        ull accA[7], accB[7];
#pragma unroll
        for (int r = 0; r < 7; r++) { accA[r] = 0ull; accB[r] = 0ull; }
        if (pid < 256) {
            const ulonglong2* wa = reinterpret_cast<const ulonglong2*>(w_ih + (size_t)A * 128);
            const ulonglong2* wb = reinterpret_cast<const ulonglong2*>(w_ih + (size_t)B * 128);
            bool doB = (B < 384);
            const ulonglong2* xg = reinterpret_cast<const ulonglong2*>(xh);
#pragma unroll 1
            for (int g = 0; g < 32; g++) {
                ulonglong2 av = wa[g];
                ulonglong2 bv;
                if (doB) bv = wb[g];
                else { bv.x = 0ull; bv.y = 0ull; }
#pragma unroll
                for (int r = 0; r < 7; r++) {
                    ulonglong2 xv = xg[(rbase + r) * 32 + g];
                    FMA2(accA[r], av.x, xv.x);
                    FMA2(accA[r], av.y, xv.y);
                    FMA2(accB[r], bv.x, xv.x);
                    FMA2(accB[r], bv.y, xv.y);
                }
            }
        }
        writeacc(accA, accB);
    };

    // GRU gates + state rotation + per-row char maxima (4 partials per row)
    auto gatephase = [&](bool step1) -> bool {
        bool changed = false;
        for (int m = tid; m < 14 * HH; m += NT) {
            int r = m >> 7, k = m & 127;
            if (r < nv) {
                float rpre = gsm[r * 608 + k];
                float zpre = gsm[r * 608 + 128 + k];
                float inp  = gsm[r * 608 + 256 + k];
                float hnp  = gsm[r * 608 + 384 + k];
                float rg = __fdividef(1.0f, 1.0f + __expf(-rpre));
                float zg = __fdividef(1.0f, 1.0f + __expf(-zpre));
                float n  = tanhf(inp + rg * hnp);
                int   xi = r * 128 + k;
                float xold = xh[xi];
                float old2 = xp2[xi];
                float hn = step1 ? (1.0f - zg) * n
                                 : (1.0f - zg) * n + zg * xold;
                changed |= (__float_as_int(hn) != __float_as_int(old2));
                xp2[xi] = xold;
                xh[xi]  = hn;
                xl[xi]  = (hn >= 0.f) ? hn : 0.01f * hn;
            }
        }
        if (tid < 56) {
            int r = tid >> 2, q = tid & 3;
            float mx = -3.4e38f;
#pragma unroll
            for (int c = 0; c < 24; c++) mx = fmaxf(mx, gsm[r * 608 + 512 + q * 24 + c]);
            m4[tid] = mx;
        }
        return changed;
    };

    const float THR = (float)(1.0 - 1e-05);

    // pre-step: hn0 = GRU(ht, 0)
    matvec1();
    __syncthreads();
    gatephase(true);
    __syncthreads();

    float cval[3], pval[3];
    int   foff[3];
    int   nslots = 0;
    int   sConv = -1;

    for (int s = 0; s < TSTEPS; s++) {
        matvec();
        __syncthreads();
        bool changed = gatephase(false);
        if (s == 0) changed = true;               // xp2 invalid at s=0
        int cnt = __syncthreads_count(changed ? 1 : 0);

#pragma unroll
        for (int q = 0; q < 3; q++) pval[q] = cval[q];
        nslots = 0;
        for (int m = tid; m < nv * CC; m += NT) {
            int r = m / CC, c = m - r * CC;
            float mx = fmaxf(fmaxf(m4[r * 4 + 0], m4[r * 4 + 1]),
                             fmaxf(m4[r * 4 + 2], m4[r * 4 + 3]));
            float ch = gsm[r * 608 + 512 + c];
            float cn = __fdiv_rn(ch, mx);
            float val = (cn > THR) ? cn : 0.f;
            int off = (base + r) * (TSTEPS * CC) + c;
            out[(size_t)off + (size_t)s * CC] = val;
            if (c == 52 && val == 1.0f && lensm[r] == 0) lensm[r] = s + 1;
            cval[nslots] = val;
            foff[nslots] = off;
            nslots++;
        }

        if (cnt == 0) { sConv = s; break; }
        __syncthreads();
    }

    if (sConv >= 0) {
        // period-2 limit cycle: outputs alternate between steps sConv-1, sConv
        for (int s2 = sConv + 1; s2 < TSTEPS; s2++) {
            bool even = (((s2 - sConv) & 1) == 0);
#pragma unroll
            for (int q = 0; q < 3; q++) {
                if (q < nslots)
                    out[(size_t)foff[q] + (size_t)s2 * CC] = even ? cval[q] : pval[q];
            }
        }
    }

    __syncthreads();
    if (hasLens && tid < nv) {
        int L = lensm[tid];
        out[(size_t)TITLES_ELEMS + base + tid] = (float)(L == 0 ? TSTEPS : L);
    }
}

// ------------------------------- launch -------------------------------------
extern "C" void kernel_launch(void* const* d_in, const int* in_sizes, int n_in,
                              void* d_out, int out_size) {
    const float* img_feat = (const float*)d_in[0];
    const float* lin1_w   = (const float*)d_in[1];
    const float* lin1_b   = (const float*)d_in[2];
    const float* w_ih     = (const float*)d_in[3];
    const float* w_hh     = (const float*)d_in[4];
    const float* b_ih     = (const float*)d_in[5];
    const float* b_hh     = (const float*)d_in[6];
    const float* lin2_w   = (const float*)d_in[7];
    const float* lin2_b   = (const float*)d_in[8];

    cudaFuncSetAttribute(fused_kernel,
                         cudaFuncAttributeMaxDynamicSharedMemorySize, SMEM_TOT);

    int hasLens = (out_size >= TITLES_ELEMS + BB) ? 1 : 0;
    fused_kernel<<<148, 608, SMEM_TOT>>>((float*)d_out, img_feat, lin1_w, lin1_b,
                                         w_ih, w_hh, b_ih, b_hh, lin2_w, lin2_b,
                                         hasLens);
}